// round 1
// baseline (speedup 1.0000x reference)
#include <cuda_runtime.h>
#include <math.h>

// Problem constants (match reference)
#define B_N     16
#define C_CH    256
#define L_LEN   8192
#define DEPTH_N 12

#define NTH     256            // threads per CTA
#define CHUNK   32             // elements per thread
#define NPAIR   16             // f32x2 pairs per thread
// pad 2 floats per 32 to kill 128B-stride bank conflicts (keeps 8B alignment)
#define PADF(e) ((e) + (((e) >> 5) << 1))
#define SM_STRIDE (L_LEN + (L_LEN / 32) * 2)   // 8704 floats per buffer

using u64 = unsigned long long;

__device__ __forceinline__ u64 pk2(float lo, float hi) {
    u64 r; asm("mov.b64 %0,{%1,%2};" : "=l"(r) : "f"(lo), "f"(hi)); return r;
}
__device__ __forceinline__ void upk2(u64 v, float& lo, float& hi) {
    asm("mov.b64 {%0,%1},%2;" : "=f"(lo), "=f"(hi) : "l"(v));
}
// packed 2xfp32 FMA (Blackwell f32x2 pipe: 2 FMA lanes per instruction)
__device__ __forceinline__ u64 fma2(u64 a, u64 b, u64 c) {
    u64 r; asm("fma.rn.f32x2 %0,%1,%2,%3;" : "=l"(r) : "l"(a), "l"(b), "l"(c)); return r;
}
__device__ __forceinline__ u64 mul2(u64 a, u64 b) {
    u64 r; asm("mul.rn.f32x2 %0,%1,%2;" : "=l"(r) : "l"(a), "l"(b)); return r;
}

// guarded pair load from padded smem; gi = even global element index (may be < 0)
__device__ __forceinline__ u64 gld2(const float* s, int gi) {
    if (gi >= 0) return *(const u64*)(s + PADF(gi));
    return 0ull;
}
__device__ __forceinline__ float gldf(const float* s, int gi) {
    return (gi >= 0) ? s[PADF(gi)] : 0.0f;
}

// One dilated-conv level in pair space. DD = dilation/2 (in pairs).
// Taps: offset 0 <-> h[3], DD <-> h[2], 2DD <-> h[1], 3DD <-> h[0].
// In-chunk taps come from registers (compile-time), halo taps from padded smem
// holding the previous level's res_lo. Descending p keeps in-place update safe.
template<int DD, bool STORE>
__device__ __forceinline__ void level_ct(
    u64 (&rl)[NPAIR], u64 (&y2)[NPAIR],
    const float* sOld, float* sNew, int pb,
    u64 a0, u64 a1, u64 a2, u64 a3,
    float wi, float e0, float e1, float e2, float e3)
{
    __syncthreads();   // previous level's smem writes visible
    const u64 b0 = pk2(wi * e0, wi * e0);
    const u64 b1 = pk2(wi * e1, wi * e1);
    const u64 b2 = pk2(wi * e2, wi * e2);
    const u64 b3 = pk2(wi * e3, wi * e3);
#pragma unroll
    for (int p = NPAIR - 1; p >= 0; --p) {
        u64 t0 = rl[p];
        u64 t1 = (p >= DD    ) ? rl[p - DD    ] : gld2(sOld, 2 * (pb + p - DD));
        u64 t2 = (p >= 2 * DD) ? rl[p - 2 * DD] : gld2(sOld, 2 * (pb + p - 2 * DD));
        u64 t3 = (p >= 3 * DD) ? rl[p - 3 * DD] : gld2(sOld, 2 * (pb + p - 3 * DD));
        y2[p] = fma2(b3, t0, fma2(b2, t1, fma2(b1, t2, fma2(b0, t3, y2[p]))));
        rl[p] = fma2(a3, t0, fma2(a2, t1, fma2(a1, t2, mul2(a0, t3))));
    }
    if (STORE) {
#pragma unroll
        for (int p = 0; p < NPAIR; ++p)
            *(u64*)(sNew + PADF(2 * (pb + p))) = rl[p];
    }
}

__global__ void __launch_bounds__(NTH, 2)
mr_kernel(const float* __restrict__ x, const float* __restrict__ h0,
          const float* __restrict__ h1, const float* __restrict__ w,
          float* __restrict__ out)
{
    extern __shared__ float sm[];
    float* bufA = sm;
    float* bufB = sm + SM_STRIDE;

    const int tid = threadIdx.x;
    const int row = blockIdx.x;           // b*C + c
    const int c   = row & (C_CH - 1);
    const float* xr   = x   + (size_t)row * L_LEN;
    float*       outr = out + (size_t)row * L_LEN;

    // ---- stage x -> bufA (padded layout), fully coalesced float2 loads ----
    const float2* x2 = (const float2*)xr;
#pragma unroll
    for (int k = 0; k < L_LEN / 2 / NTH; ++k) {
        int p2 = tid + k * NTH;
        float2 v = x2[p2];
        *(float2*)(bufA + PADF(2 * p2)) = v;
    }

    // ---- per-channel coefficients (uniform broadcast loads) ----
    const float c0 = __ldg(h0 + c * 4 + 0), c1 = __ldg(h0 + c * 4 + 1);
    const float c2 = __ldg(h0 + c * 4 + 2), c3 = __ldg(h0 + c * 4 + 3);
    const float e0 = __ldg(h1 + c * 4 + 0), e1 = __ldg(h1 + c * 4 + 1);
    const float e2 = __ldg(h1 + c * 4 + 2), e3 = __ldg(h1 + c * 4 + 3);
    const float* wc = w + c * (DEPTH_N + 2);

    __syncthreads();

    const int base = tid * CHUNK;
    const int pb   = tid * NPAIR;

    // ---- load own chunk into scalar registers ----
    float f[CHUNK];
#pragma unroll
    for (int p = 0; p < NPAIR; ++p) {
        float lo, hi;
        upk2(*(const u64*)(bufA + PADF(2 * (pb + p))), lo, hi);
        f[2 * p] = lo; f[2 * p + 1] = hi;
    }

    // ---- level d=1 (scalar; odd offsets don't pair-align) + y init ----
    // y = w13*x + w12*(h1 conv d=1);  res_lo = h0 conv d=1
    u64 rl[NPAIR], y2[NPAIR];
    {
        const float w13 = __ldg(wc + 13);
        const float w12 = __ldg(wc + 12);
        const float g0 = w12 * e0, g1 = w12 * e1, g2 = w12 * e2;
        const float g3 = w13 + w12 * e3;   // fold y-init into the t0 coefficient
#pragma unroll
        for (int p = 0; p < NPAIR; ++p) {
            // taps read OLD f (pre-level values) only -> ascending p is safe
            const int j0 = 2 * p, j1 = 2 * p + 1;
            float u0 = f[j0];
            float u1 = (j0 >= 1) ? f[j0 - 1] : gldf(bufA, base + j0 - 1);
            float u2 = (j0 >= 2) ? f[j0 - 2] : gldf(bufA, base + j0 - 2);
            float u3 = (j0 >= 3) ? f[j0 - 3] : gldf(bufA, base + j0 - 3);
            float v0 = f[j1];
            float v1 = u0, v2 = u1, v3 = u2;
            float ylo = fmaf(g3, u0, fmaf(g2, u1, fmaf(g1, u2, g0 * u3)));
            float yhi = fmaf(g3, v0, fmaf(g2, v1, fmaf(g1, v2, g0 * v3)));
            float nlo = fmaf(c3, u0, fmaf(c2, u1, fmaf(c1, u2, c0 * u3)));
            float nhi = fmaf(c3, v0, fmaf(c2, v1, fmaf(c1, v2, c0 * v3)));
            y2[p] = pk2(ylo, yhi);
            rl[p] = pk2(nlo, nhi);
            *(u64*)(bufB + PADF(2 * (pb + p))) = rl[p];   // new res_lo -> bufB
        }
    }

    const u64 a0 = pk2(c0, c0), a1 = pk2(c1, c1), a2 = pk2(c2, c2), a3 = pk2(c3, c3);

    float* sO = bufB;   // holds res_lo after d=1
    float* sN = bufA;

    // ---- levels d=2..2048 (DD = d/2 in pair space), w columns 11..1 ----
    level_ct<1,    true >(rl, y2, sO, sN, pb, a0, a1, a2, a3, __ldg(wc + 11), e0, e1, e2, e3); { float* t = sO; sO = sN; sN = t; }
    level_ct<2,    true >(rl, y2, sO, sN, pb, a0, a1, a2, a3, __ldg(wc + 10), e0, e1, e2, e3); { float* t = sO; sO = sN; sN = t; }
    level_ct<4,    true >(rl, y2, sO, sN, pb, a0, a1, a2, a3, __ldg(wc +  9), e0, e1, e2, e3); { float* t = sO; sO = sN; sN = t; }
    level_ct<8,    true >(rl, y2, sO, sN, pb, a0, a1, a2, a3, __ldg(wc +  8), e0, e1, e2, e3); { float* t = sO; sO = sN; sN = t; }
    level_ct<16,   true >(rl, y2, sO, sN, pb, a0, a1, a2, a3, __ldg(wc +  7), e0, e1, e2, e3); { float* t = sO; sO = sN; sN = t; }
    level_ct<32,   true >(rl, y2, sO, sN, pb, a0, a1, a2, a3, __ldg(wc +  6), e0, e1, e2, e3); { float* t = sO; sO = sN; sN = t; }
    level_ct<64,   true >(rl, y2, sO, sN, pb, a0, a1, a2, a3, __ldg(wc +  5), e0, e1, e2, e3); { float* t = sO; sO = sN; sN = t; }
    level_ct<128,  true >(rl, y2, sO, sN, pb, a0, a1, a2, a3, __ldg(wc +  4), e0, e1, e2, e3); { float* t = sO; sO = sN; sN = t; }
    level_ct<256,  true >(rl, y2, sO, sN, pb, a0, a1, a2, a3, __ldg(wc +  3), e0, e1, e2, e3); { float* t = sO; sO = sN; sN = t; }
    level_ct<512,  true >(rl, y2, sO, sN, pb, a0, a1, a2, a3, __ldg(wc +  2), e0, e1, e2, e3); { float* t = sO; sO = sN; sN = t; }
    level_ct<1024, false>(rl, y2, sO, sN, pb, a0, a1, a2, a3, __ldg(wc +  1), e0, e1, e2, e3);
    // sN was last READ two levels ago; every thread passed the last level's
    // __syncthreads() before arriving here -> safe to reuse sN as staging.

    // ---- final: y += w0 * res_lo; exact GELU; stage to smem ----
    {
        const float w0v = __ldg(wc + 0);
        const u64 w0p = pk2(w0v, w0v);
#pragma unroll
        for (int p = 0; p < NPAIR; ++p) {
            u64 yf = fma2(w0p, rl[p], y2[p]);
            float lo, hi; upk2(yf, lo, hi);
            lo = 0.5f * lo * (1.0f + erff(lo * 0.70710678118654752f));
            hi = 0.5f * hi * (1.0f + erff(hi * 0.70710678118654752f));
            *(float2*)(sN + PADF(2 * (pb + p))) = make_float2(lo, hi);
        }
    }
    __syncthreads();

    // ---- coalesced float2 store to global ----
    float2* o2 = (float2*)outr;
#pragma unroll
    for (int k = 0; k < L_LEN / 2 / NTH; ++k) {
        int p2 = tid + k * NTH;
        o2[p2] = *(const float2*)(sN + PADF(2 * p2));
    }
}

extern "C" void kernel_launch(void* const* d_in, const int* in_sizes, int n_in,
                              void* d_out, int out_size)
{
    (void)in_sizes; (void)n_in; (void)out_size;
    const float* x  = (const float*)d_in[0];
    const float* h0 = (const float*)d_in[1];
    const float* h1 = (const float*)d_in[2];
    const float* w  = (const float*)d_in[3];
    float* out = (float*)d_out;

    const int smem_bytes = 2 * SM_STRIDE * (int)sizeof(float);   // 69,632 B
    cudaFuncSetAttribute(mr_kernel, cudaFuncAttributeMaxDynamicSharedMemorySize, smem_bytes);
    mr_kernel<<<B_N * C_CH, NTH, smem_bytes>>>(x, h0, h1, w, out);
}

// round 2
// speedup vs baseline: 1.0066x; 1.0066x over previous
#include <cuda_runtime.h>
#include <math.h>

// Problem constants
#define B_N     16
#define C_CH    256
#define L_LEN   8192
#define DEPTH_N 12

#define NTH     256            // threads per CTA
#define CHUNK   32             // elements per thread (one 136B padded block)
#define NPAIR   16             // f32x2 pairs per thread
#define SM_STRIDE 8704         // floats per buffer: 8192 + 2 pad per 32

using u64 = unsigned long long;

// relative padded-word offset from a 32-element-aligned base (e in words, may be <0)
__host__ __device__ constexpr int padrel(int e) {
    int q = (e >= 0) ? (e / 32) : -(((31 - e) / 32));   // floor(e/32)
    return e + 2 * q;
}

__device__ __forceinline__ u64 pk2(float lo, float hi) {
    u64 r; asm("mov.b64 %0,{%1,%2};" : "=l"(r) : "f"(lo), "f"(hi)); return r;
}
__device__ __forceinline__ void upk2(u64 v, float& lo, float& hi) {
    asm("mov.b64 {%0,%1},%2;" : "=f"(lo), "=f"(hi) : "l"(v));
}
__device__ __forceinline__ u64 fma2(u64 a, u64 b, u64 c) {
    u64 r; asm("fma.rn.f32x2 %0,%1,%2,%3;" : "=l"(r) : "l"(a), "l"(b), "l"(c)); return r;
}
__device__ __forceinline__ u64 mul2(u64 a, u64 b) {
    u64 r; asm("mul.rn.f32x2 %0,%1,%2;" : "=l"(r) : "l"(a), "l"(b)); return r;
}

// One dilated level in pair space. DD = dilation/2 (pairs).
// ob/nb: this thread's own 136B-block base in old/new buffer.
// zs: 128B zero slot (reads zs+8p give 0).
template<int DD, bool STORE>
__device__ __forceinline__ void level_f(
    u64 (&rl)[NPAIR], u64 (&y2)[NPAIR],
    const char* ob, char* nb, const char* zs,
    int tid, bool ge1, bool ge2,
    u64 a0, u64 a1, u64 a2, u64 a3,
    u64 b0, u64 b1, u64 b2, u64 b3)
{
    __syncthreads();   // previous level's smem writes visible
    if (DD >= 16) {
        // tap offsets are whole-chunk multiples; guards are uniform in p.
        const char* p1 = (tid >= 1 * DD / 16) ? ob - (1 * DD / 16) * 136 : zs;
        const char* p2 = (tid >= 2 * DD / 16) ? ob - (2 * DD / 16) * 136 : zs;
        const char* p3 = (tid >= 3 * DD / 16) ? ob - (3 * DD / 16) * 136 : zs;
#pragma unroll
        for (int p = NPAIR - 1; p >= 0; --p) {
            u64 t0 = rl[p];
            u64 t1 = *(const u64*)(p1 + 8 * p);
            u64 t2 = *(const u64*)(p2 + 8 * p);
            u64 t3 = *(const u64*)(p3 + 8 * p);
            y2[p] = fma2(b3, t0, fma2(b2, t1, fma2(b1, t2, fma2(b0, t3, y2[p]))));
            rl[p] = fma2(a3, t0, fma2(a2, t1, fma2(a1, t2, mul2(a0, t3))));
        }
    } else {
#pragma unroll
        for (int p = NPAIR - 1; p >= 0; --p) {
            u64 t0 = rl[p];
            u64 t1, t2, t3;
            if (p >= 1 * DD) t1 = rl[p - 1 * DD];
            else {
                t1 = 0;
                const bool ok = ((1 * DD - p + 15) / 16 <= 1) ? ge1 : ge2;
                if (ok) t1 = *(const u64*)(ob + 4 * padrel(2 * (p - 1 * DD)));
            }
            if (p >= 2 * DD) t2 = rl[p - 2 * DD];
            else {
                t2 = 0;
                const bool ok = ((2 * DD - p + 15) / 16 <= 1) ? ge1 : ge2;
                if (ok) t2 = *(const u64*)(ob + 4 * padrel(2 * (p - 2 * DD)));
            }
            if (p >= 3 * DD) t3 = rl[p - 3 * DD];
            else {
                t3 = 0;
                const bool ok = ((3 * DD - p + 15) / 16 <= 1) ? ge1 : ge2;
                if (ok) t3 = *(const u64*)(ob + 4 * padrel(2 * (p - 3 * DD)));
            }
            y2[p] = fma2(b3, t0, fma2(b2, t1, fma2(b1, t2, fma2(b0, t3, y2[p]))));
            rl[p] = fma2(a3, t0, fma2(a2, t1, fma2(a1, t2, mul2(a0, t3))));
        }
    }
    if (STORE) {
#pragma unroll
        for (int p = 0; p < NPAIR; ++p)
            *(u64*)(nb + 8 * p) = rl[p];
    }
}

__global__ void __launch_bounds__(NTH, 2)
mr_kernel(const float* __restrict__ x, const float* __restrict__ h0,
          const float* __restrict__ h1, const float* __restrict__ w,
          float* __restrict__ out)
{
    extern __shared__ float sm[];
    char* sA = (char*)sm;
    char* sB = (char*)sm + SM_STRIDE * 4;
    char* zs = (char*)sm + 2 * SM_STRIDE * 4;   // 128B zero slot

    const int tid = threadIdx.x;
    const int row = blockIdx.x;                  // b*C + c
    const int c   = row & (C_CH - 1);
    const float* xr   = x   + (size_t)row * L_LEN;
    float*       outr = out + (size_t)row * L_LEN;

    const bool ge1 = (tid >= 1);
    const bool ge2 = (tid >= 2);

    // zero the guard slot
    if (tid < 16) *(u64*)(zs + 8 * tid) = 0ull;

    // ---- load own 32-element chunk straight into registers (LDG.128 x8) ----
    float f[CHUNK];
    const float4* x4 = (const float4*)xr + tid * 8;
#pragma unroll
    for (int i = 0; i < 8; ++i) {
        float4 v = x4[i];
        f[4 * i] = v.x; f[4 * i + 1] = v.y; f[4 * i + 2] = v.z; f[4 * i + 3] = v.w;
    }

    // own-chunk bases in padded buffers
    char* oA = sA + 136 * tid;
    char* oB = sB + 136 * tid;

    // stage x into bufA (padded) for level-1 halos
#pragma unroll
    for (int p = 0; p < NPAIR; ++p)
        *(u64*)(oA + 8 * p) = pk2(f[2 * p], f[2 * p + 1]);

    // ---- per-channel coefficients ----
    const float c0 = __ldg(h0 + c * 4 + 0), c1 = __ldg(h0 + c * 4 + 1);
    const float c2 = __ldg(h0 + c * 4 + 2), c3 = __ldg(h0 + c * 4 + 3);
    const float e0 = __ldg(h1 + c * 4 + 0), e1 = __ldg(h1 + c * 4 + 1);
    const float e2 = __ldg(h1 + c * 4 + 2), e3 = __ldg(h1 + c * 4 + 3);
    const float* wc = w + c * (DEPTH_N + 2);

    __syncthreads();   // staging + zero slot visible

    // ---- level d=1 (scalar) + y init ----
    u64 rl[NPAIR], y2[NPAIR];
    {
        // halo elements -1,-2,-3 at compile-time byte offsets from own base
        float xm1 = ge1 ? *(const float*)(oA - 12) : 0.0f;  // padrel(-1)=-3
        float xm2 = ge1 ? *(const float*)(oA - 16) : 0.0f;  // padrel(-2)=-4
        float xm3 = ge1 ? *(const float*)(oA - 20) : 0.0f;  // padrel(-3)=-5

        const float w13 = __ldg(wc + 13);
        const float w12 = __ldg(wc + 12);
        const float g0 = w12 * e0, g1 = w12 * e1, g2 = w12 * e2;
        const float g3 = w13 + w12 * e3;      // fold y = w13*x into the t0 tap
#pragma unroll
        for (int p = 0; p < NPAIR; ++p) {
            const int j0 = 2 * p, j1 = 2 * p + 1;
            float u0 = f[j0];
            float u1 = (j0 >= 1) ? f[j0 - 1] : xm1;
            float u2 = (j0 >= 2) ? f[j0 - 2] : xm2;
            float u3 = (j0 >= 3) ? f[j0 - 3] : ((j0 == 2) ? xm1 : xm3);
            float v0 = f[j1], v1 = u0, v2 = u1, v3 = u2;
            float ylo = fmaf(g3, u0, fmaf(g2, u1, fmaf(g1, u2, g0 * u3)));
            float yhi = fmaf(g3, v0, fmaf(g2, v1, fmaf(g1, v2, g0 * v3)));
            float nlo = fmaf(c3, u0, fmaf(c2, u1, fmaf(c1, u2, c0 * u3)));
            float nhi = fmaf(c3, v0, fmaf(c2, v1, fmaf(c1, v2, c0 * v3)));
            y2[p] = pk2(ylo, yhi);
            rl[p] = pk2(nlo, nhi);
            *(u64*)(oB + 8 * p) = rl[p];      // res_lo -> bufB
        }
    }

    const u64 a0 = pk2(c0, c0), a1 = pk2(c1, c1), a2 = pk2(c2, c2), a3 = pk2(c3, c3);

#define RUN_LEVEL(DDV, ST, OB, NB, WI)                                          \
    {                                                                            \
        const float wi = __ldg(wc + (WI));                                       \
        const u64 b0 = pk2(wi * e0, wi * e0);                                    \
        const u64 b1 = pk2(wi * e1, wi * e1);                                    \
        const u64 b2 = pk2(wi * e2, wi * e2);                                    \
        const u64 b3 = pk2(wi * e3, wi * e3);                                    \
        level_f<DDV, ST>(rl, y2, OB, NB, zs, tid, ge1, ge2,                      \
                         a0, a1, a2, a3, b0, b1, b2, b3);                        \
    }

    // levels d=2..2048 (DD = d/2 in pair space), w columns 11..1
    RUN_LEVEL(1,    true,  oB, oA, 11)
    RUN_LEVEL(2,    true,  oA, oB, 10)
    RUN_LEVEL(4,    true,  oB, oA,  9)
    RUN_LEVEL(8,    true,  oA, oB,  8)
    RUN_LEVEL(16,   true,  oB, oA,  7)
    RUN_LEVEL(32,   true,  oA, oB,  6)
    RUN_LEVEL(64,   true,  oB, oA,  5)
    RUN_LEVEL(128,  true,  oA, oB,  4)
    RUN_LEVEL(256,  true,  oB, oA,  3)
    RUN_LEVEL(512,  true,  oA, oB,  2)
    RUN_LEVEL(1024, false, oB, oA,  1)
#undef RUN_LEVEL

    // ---- final: y += w0 * res_lo; exact GELU; direct STG.128 ----
    {
        const float w0v = __ldg(wc + 0);
        const u64 w0p = pk2(w0v, w0v);
        float4* o4 = (float4*)outr + tid * 8;
#pragma unroll
        for (int q = 0; q < 8; ++q) {
            u64 ya = fma2(w0p, rl[2 * q],     y2[2 * q]);
            u64 yb = fma2(w0p, rl[2 * q + 1], y2[2 * q + 1]);
            float a, bb, cc, dd;
            upk2(ya, a, bb);
            upk2(yb, cc, dd);
            a  = 0.5f * a  * (1.0f + erff(a  * 0.70710678118654752f));
            bb = 0.5f * bb * (1.0f + erff(bb * 0.70710678118654752f));
            cc = 0.5f * cc * (1.0f + erff(cc * 0.70710678118654752f));
            dd = 0.5f * dd * (1.0f + erff(dd * 0.70710678118654752f));
            o4[q] = make_float4(a, bb, cc, dd);
        }
    }
}

extern "C" void kernel_launch(void* const* d_in, const int* in_sizes, int n_in,
                              void* d_out, int out_size)
{
    (void)in_sizes; (void)n_in; (void)out_size;
    const float* x  = (const float*)d_in[0];
    const float* h0 = (const float*)d_in[1];
    const float* h1 = (const float*)d_in[2];
    const float* w  = (const float*)d_in[3];
    float* out = (float*)d_out;

    const int smem_bytes = 2 * SM_STRIDE * (int)sizeof(float) + 136;  // 69,768 B
    cudaFuncSetAttribute(mr_kernel, cudaFuncAttributeMaxDynamicSharedMemorySize, smem_bytes);
    mr_kernel<<<B_N * C_CH, NTH, smem_bytes>>>(x, h0, h1, w, out);
}

// round 3
// speedup vs baseline: 1.2088x; 1.2009x over previous
#include <cuda_runtime.h>
#include <math.h>

#define B_N     16
#define C_CH    256
#define L_LEN   8192
#define DEPTH_N 12

#define NTH     256
#define NSLOT   16             // pairs per thread
#define SM_STRIDE 8704         // floats per buffer (8192 + 2 pad per 32 floats)
#define BUFB    (SM_STRIDE * 4)

using u64 = unsigned long long;

// padded relative word offset for element index e (may be < 0): e + 2*floor(e/32)
__host__ __device__ constexpr int padrel(int e) {
    int q = (e >= 0) ? (e / 32) : -(((31 - e) / 32));
    return e + 2 * q;
}

__device__ __forceinline__ u64 pk2(float lo, float hi) {
    u64 r; asm("mov.b64 %0,{%1,%2};" : "=l"(r) : "f"(lo), "f"(hi)); return r;
}
__device__ __forceinline__ void upk2(u64 v, float& lo, float& hi) {
    asm("mov.b64 {%0,%1},%2;" : "=f"(lo), "=f"(hi) : "l"(v));
}
__device__ __forceinline__ u64 fma2(u64 a, u64 b, u64 c) {
    u64 r; asm("fma.rn.f32x2 %0,%1,%2,%3;" : "=l"(r) : "l"(a), "l"(b), "l"(c)); return r;
}
__device__ __forceinline__ u64 mul2(u64 a, u64 b) {
    u64 r; asm("mul.rn.f32x2 %0,%1,%2;" : "=l"(r) : "l"(a), "l"(b)); return r;
}

// ---------- Phase A: block layout (thread owns pairs 16t..16t+15) ----------
// DD = tap spacing in pairs (1,2,4,8). SF = first slot to store for next level.
template<int DD, int SF>
__device__ __forceinline__ void levelA(
    u64 (&rl)[NSLOT], u64 (&y2)[NSLOT], const char* ob, char* nb,
    bool ge1, bool ge2,
    u64 a0, u64 a1, u64 a2, u64 a3,
    u64 b0, u64 b1, u64 b2, u64 b3)
{
    __syncthreads();
#pragma unroll
    for (int p = NSLOT - 1; p >= 0; --p) {
        u64 t0 = rl[p];
        u64 t1, t2, t3;
        if (p >= 1 * DD) t1 = rl[p - 1 * DD];
        else { bool ok = ((1 * DD - p + 15) / 16 <= 1) ? ge1 : ge2;
               t1 = ok ? *(const u64*)(ob + 4 * padrel(2 * (p - 1 * DD))) : 0; }
        if (p >= 2 * DD) t2 = rl[p - 2 * DD];
        else { bool ok = ((2 * DD - p + 15) / 16 <= 1) ? ge1 : ge2;
               t2 = ok ? *(const u64*)(ob + 4 * padrel(2 * (p - 2 * DD))) : 0; }
        if (p >= 3 * DD) t3 = rl[p - 3 * DD];
        else { bool ok = ((3 * DD - p + 15) / 16 <= 1) ? ge1 : ge2;
               t3 = ok ? *(const u64*)(ob + 4 * padrel(2 * (p - 3 * DD))) : 0; }
        y2[p] = fma2(b3, t0, fma2(b2, t1, fma2(b1, t2, fma2(b0, t3, y2[p]))));
        rl[p] = fma2(a3, t0, fma2(a2, t1, fma2(a1, t2, mul2(a0, t3))));
    }
#pragma unroll
    for (int p = SF; p < NSLOT; ++p)
        *(u64*)(nb + 8 * p) = rl[p];
}

// ---------- Phase B: tile16 layout (thread (T,r) owns pairs 256T + r + 16j) ----------
// DJ = tap spacing in slots (1,2,4,8). Remote tap at byte offset 136*(j-DJ*m) from own base.
template<int DJ, int SF, bool STORE>
__device__ __forceinline__ void levelB(
    u64 (&rl)[NSLOT], u64 (&y2)[NSLOT], const char* ob, char* nb,
    bool tge1, bool tge2,
    u64 a0, u64 a1, u64 a2, u64 a3,
    u64 b0, u64 b1, u64 b2, u64 b3)
{
    __syncthreads();
#pragma unroll
    for (int j = NSLOT - 1; j >= 0; --j) {
        u64 t0 = rl[j];
        u64 t1, t2, t3;
        if (j >= 1 * DJ) t1 = rl[j - 1 * DJ];
        else { bool ok = (1 * DJ - j <= 16) ? tge1 : tge2;
               t1 = ok ? *(const u64*)(ob + 136 * (j - 1 * DJ)) : 0; }
        if (j >= 2 * DJ) t2 = rl[j - 2 * DJ];
        else { bool ok = (2 * DJ - j <= 16) ? tge1 : tge2;
               t2 = ok ? *(const u64*)(ob + 136 * (j - 2 * DJ)) : 0; }
        if (j >= 3 * DJ) t3 = rl[j - 3 * DJ];
        else { bool ok = (3 * DJ - j <= 16) ? tge1 : tge2;
               t3 = ok ? *(const u64*)(ob + 136 * (j - 3 * DJ)) : 0; }
        y2[j] = fma2(b3, t0, fma2(b2, t1, fma2(b1, t2, fma2(b0, t3, y2[j]))));
        rl[j] = fma2(a3, t0, fma2(a2, t1, fma2(a1, t2, mul2(a0, t3))));
    }
    if (STORE) {
#pragma unroll
        for (int j = SF; j < NSLOT; ++j)
            *(u64*)(nb + 136 * j) = rl[j];
    }
}

// ---------- Phase C: cyclic-256 layout (thread owns pairs t + 256k) ----------
// DK = tap spacing in slots (1,2,4). Pure register level: no smem, no sync.
template<int DK>
__device__ __forceinline__ void levelC(
    u64 (&rl)[NSLOT], u64 (&y2)[NSLOT],
    u64 a0, u64 a1, u64 a2, u64 a3,
    u64 b0, u64 b1, u64 b2, u64 b3)
{
#pragma unroll
    for (int k = NSLOT - 1; k >= 0; --k) {
        u64 t0 = rl[k];
        u64 t1 = (k >= 1 * DK) ? rl[k - 1 * DK] : 0;
        u64 t2 = (k >= 2 * DK) ? rl[k - 2 * DK] : 0;
        u64 t3 = (k >= 3 * DK) ? rl[k - 3 * DK] : 0;
        y2[k] = fma2(b3, t0, fma2(b2, t1, fma2(b1, t2, fma2(b0, t3, y2[k]))));
        rl[k] = fma2(a3, t0, fma2(a2, t1, fma2(a1, t2, mul2(a0, t3))));
    }
}

__global__ void __launch_bounds__(NTH, 2)
mr_kernel(const float* __restrict__ x, const float* __restrict__ h0,
          const float* __restrict__ h1, const float* __restrict__ w,
          float* __restrict__ out)
{
    extern __shared__ float sm[];
    char* B0 = (char*)sm;
    char* B1 = (char*)sm + BUFB;
    float* scr = (float*)((char*)sm + 2 * BUFB);   // 8 warps x 3 floats

    const int tid  = threadIdx.x;
    const int lane = tid & 31;
    const int warp = tid >> 5;
    const int T    = tid >> 4;        // tile index (tile16 layout)
    const int rr   = tid & 15;        // lane-in-tile
    const int row  = blockIdx.x;      // b*C + c
    const int c    = row & (C_CH - 1);
    const float* xr   = x   + (size_t)row * L_LEN;
    float*       outr = out + (size_t)row * L_LEN;

    const bool ge1  = (tid >= 1), ge2 = (tid >= 2);
    const bool tge1 = (T >= 1),  tge2 = (T >= 2);

    // layout base pointers (byte(p) = 8p + 8*(p>>4), pair-linear padded)
    char* blk0 = B0 + 136 * tid;
    char* blk1 = B1 + 136 * tid;
    char* til0 = B0 + 2176 * T + 8 * rr;
    char* til1 = B1 + 2176 * T + 8 * rr;
    char* cyc0 = B0 + 8 * tid + 8 * (tid >> 4);
    char* cyc1 = B1 + 8 * tid + 8 * (tid >> 4);

    // ---- load own 32 elements ----
    float f[32];
    const float4* x4 = (const float4*)xr + tid * 8;
#pragma unroll
    for (int i = 0; i < 8; ++i) {
        float4 v = x4[i];
        f[4 * i] = v.x; f[4 * i + 1] = v.y; f[4 * i + 2] = v.z; f[4 * i + 3] = v.w;
    }
    if (lane == 31) {           // cross-warp x halo for d=1
        scr[3 * warp + 0] = f[29];
        scr[3 * warp + 1] = f[30];
        scr[3 * warp + 2] = f[31];
    }

    // ---- per-channel coefficients ----
    const float c0 = __ldg(h0 + c * 4 + 0), c1 = __ldg(h0 + c * 4 + 1);
    const float c2 = __ldg(h0 + c * 4 + 2), c3 = __ldg(h0 + c * 4 + 3);
    const float e0 = __ldg(h1 + c * 4 + 0), e1 = __ldg(h1 + c * 4 + 1);
    const float e2 = __ldg(h1 + c * 4 + 2), e3 = __ldg(h1 + c * 4 + 3);
    const float* wc = w + c * (DEPTH_N + 2);

    // x halo elements -1,-2,-3 via shuffle (lane 0 via scratch)
    float xm1 = __shfl_up_sync(0xffffffffu, f[31], 1);
    float xm2 = __shfl_up_sync(0xffffffffu, f[30], 1);
    float xm3 = __shfl_up_sync(0xffffffffu, f[29], 1);
    __syncthreads();
    if (lane == 0) {
        if (tid > 0) {
            xm1 = scr[3 * (warp - 1) + 2];
            xm2 = scr[3 * (warp - 1) + 1];
            xm3 = scr[3 * (warp - 1) + 0];
        } else { xm1 = 0.0f; xm2 = 0.0f; xm3 = 0.0f; }
    }

    // ---- level d=1 (scalar) + y init:  y = w13*x + w12*conv(x,h1,1); rl = conv(x,h0,1) ----
    u64 rl[NSLOT], y2[NSLOT];
    {
        const float w13 = __ldg(wc + 13);
        const float w12 = __ldg(wc + 12);
        const float g0 = w12 * e0, g1 = w12 * e1, g2 = w12 * e2;
        const float g3 = w13 + w12 * e3;
#pragma unroll
        for (int p = 0; p < NSLOT; ++p) {
            const int j0 = 2 * p, j1 = 2 * p + 1;
            float u0 = f[j0];
            float u1 = (j0 >= 1) ? f[j0 - 1] : xm1;
            float u2 = (j0 >= 2) ? f[j0 - 2] : xm2;
            float u3 = (j0 >= 3) ? f[j0 - 3] : ((j0 == 2) ? xm1 : xm3);
            float v0 = f[j1], v1 = u0, v2 = u1, v3 = u2;
            float ylo = fmaf(g3, u0, fmaf(g2, u1, fmaf(g1, u2, g0 * u3)));
            float yhi = fmaf(g3, v0, fmaf(g2, v1, fmaf(g1, v2, g0 * v3)));
            float nlo = fmaf(c3, u0, fmaf(c2, u1, fmaf(c1, u2, c0 * u3)));
            float nhi = fmaf(c3, v0, fmaf(c2, v1, fmaf(c1, v2, c0 * v3)));
            y2[p] = pk2(ylo, yhi);
            rl[p] = pk2(nlo, nhi);
        }
        // store only the slots d=2's remote taps read (slots 13..15)
#pragma unroll
        for (int p = 13; p < NSLOT; ++p)
            *(u64*)(blk0 + 8 * p) = rl[p];
    }

    const u64 a0 = pk2(c0, c0), a1 = pk2(c1, c1), a2 = pk2(c2, c2), a3 = pk2(c3, c3);

#define COEFFS(WI)                                                              \
        const float wi = __ldg(wc + (WI));                                      \
        const u64 b0 = pk2(wi * e0, wi * e0);                                   \
        const u64 b1 = pk2(wi * e1, wi * e1);                                   \
        const u64 b2 = pk2(wi * e2, wi * e2);                                   \
        const u64 b3 = pk2(wi * e3, wi * e3);

    // ---- Phase A: d=2,4,8,16 ----
    { COEFFS(11) levelA<1, 10>(rl, y2, blk0, blk1, ge1, ge2, a0, a1, a2, a3, b0, b1, b2, b3); }
    { COEFFS(10) levelA<2,  4>(rl, y2, blk1, blk0, ge1, ge2, a0, a1, a2, a3, b0, b1, b2, b3); }
    { COEFFS( 9) levelA<4,  0>(rl, y2, blk0, blk1, ge1, ge2, a0, a1, a2, a3, b0, b1, b2, b3); }
    { COEFFS( 8) levelA<8,  0>(rl, y2, blk1, blk0, ge1, ge2, a0, a1, a2, a3, b0, b1, b2, b3); }

    // ---- T1: block -> tile16 (y2 through smem; rl re-read from d=16's store) ----
    __syncthreads();
#pragma unroll
    for (int j = 0; j < NSLOT; ++j)
        *(u64*)(blk1 + 8 * j) = y2[j];
    __syncthreads();
#pragma unroll
    for (int j = 0; j < NSLOT; ++j) {
        y2[j] = *(const u64*)(til1 + 136 * j);
        rl[j] = *(const u64*)(til0 + 136 * j);
    }

    // ---- Phase B: d=32,64,128,256 ----
    { COEFFS(7) levelB<1, 10, true >(rl, y2, til0, til1, tge1, tge2, a0, a1, a2, a3, b0, b1, b2, b3); }
    { COEFFS(6) levelB<2,  4, true >(rl, y2, til1, til0, tge1, tge2, a0, a1, a2, a3, b0, b1, b2, b3); }
    { COEFFS(5) levelB<4,  0, true >(rl, y2, til0, til1, tge1, tge2, a0, a1, a2, a3, b0, b1, b2, b3); }
    { COEFFS(4) levelB<8,  0, true >(rl, y2, til1, til0, tge1, tge2, a0, a1, a2, a3, b0, b1, b2, b3); }

    // ---- T2: tile16 -> cyclic-256 ----
    __syncthreads();
#pragma unroll
    for (int j = 0; j < NSLOT; ++j)
        *(u64*)(til1 + 136 * j) = y2[j];
    __syncthreads();
#pragma unroll
    for (int k = 0; k < NSLOT; ++k) {
        y2[k] = *(const u64*)(cyc1 + 2176 * k);
        rl[k] = *(const u64*)(cyc0 + 2176 * k);
    }

    // ---- Phase C: d=512,1024,2048 — pure register ----
    { COEFFS(3) levelC<1>(rl, y2, a0, a1, a2, a3, b0, b1, b2, b3); }
    { COEFFS(2) levelC<2>(rl, y2, a0, a1, a2, a3, b0, b1, b2, b3); }
    { COEFFS(1) levelC<4>(rl, y2, a0, a1, a2, a3, b0, b1, b2, b3); }
#undef COEFFS

    // ---- final: y += w0*res_lo; exact GELU; coalesced STG.64 (cyclic) ----
    {
        const float w0v = __ldg(wc + 0);
        const u64 w0p = pk2(w0v, w0v);
        float2* o2 = (float2*)outr;
#pragma unroll
        for (int k = 0; k < NSLOT; ++k) {
            u64 yf = fma2(w0p, rl[k], y2[k]);
            float lo, hi; upk2(yf, lo, hi);
            lo = 0.5f * lo * (1.0f + erff(lo * 0.70710678118654752f));
            hi = 0.5f * hi * (1.0f + erff(hi * 0.70710678118654752f));
            o2[tid + 256 * k] = make_float2(lo, hi);
        }
    }
}

extern "C" void kernel_launch(void* const* d_in, const int* in_sizes, int n_in,
                              void* d_out, int out_size)
{
    (void)in_sizes; (void)n_in; (void)out_size;
    const float* x  = (const float*)d_in[0];
    const float* h0 = (const float*)d_in[1];
    const float* h1 = (const float*)d_in[2];
    const float* w  = (const float*)d_in[3];
    float* out = (float*)d_out;

    const int smem_bytes = 2 * BUFB + 128;   // 69,760 B
    cudaFuncSetAttribute(mr_kernel, cudaFuncAttributeMaxDynamicSharedMemorySize, smem_bytes);
    mr_kernel<<<B_N * C_CH, NTH, smem_bytes>>>(x, h0, h1, w, out);
}

// round 4
// speedup vs baseline: 1.2190x; 1.0084x over previous
#include <cuda_runtime.h>
#include <math.h>

#define B_N     16
#define C_CH    256
#define L_LEN   8192
#define DEPTH_N 12

#define NTH     256
#define NSLOT   16             // pairs per thread
#define SM_STRIDE 8704         // floats per buffer (8192 + 2 pad per 32 floats)
#define BUFB    (SM_STRIDE * 4)

using u64 = unsigned long long;

// padded relative word offset for element index e (may be < 0): e + 2*floor(e/32)
__host__ __device__ constexpr int padrel(int e) {
    int q = (e >= 0) ? (e / 32) : -(((31 - e) / 32));
    return e + 2 * q;
}

__device__ __forceinline__ u64 pk2(float lo, float hi) {
    u64 r; asm("mov.b64 %0,{%1,%2};" : "=l"(r) : "f"(lo), "f"(hi)); return r;
}
__device__ __forceinline__ void upk2(u64 v, float& lo, float& hi) {
    asm("mov.b64 {%0,%1},%2;" : "=f"(lo), "=f"(hi) : "l"(v));
}
__device__ __forceinline__ u64 fma2(u64 a, u64 b, u64 c) {
    u64 r; asm("fma.rn.f32x2 %0,%1,%2,%3;" : "=l"(r) : "l"(a), "l"(b), "l"(c)); return r;
}
__device__ __forceinline__ u64 mul2(u64 a, u64 b) {
    u64 r; asm("mul.rn.f32x2 %0,%1,%2;" : "=l"(r) : "l"(a), "l"(b)); return r;
}

// ---------- Phase A: block layout (thread owns pairs 16t..16t+15) ----------
template<int DD, int SF>
__device__ __forceinline__ void levelA(
    u64 (&rl)[NSLOT], u64 (&y2)[NSLOT], const char* ob, char* nb,
    bool ge1, bool ge2,
    u64 a0, u64 a1, u64 a2, u64 a3,
    u64 b0, u64 b1, u64 b2, u64 b3)
{
    __syncthreads();
#pragma unroll
    for (int p = NSLOT - 1; p >= 0; --p) {
        u64 t0 = rl[p];
        u64 t1, t2, t3;
        if (p >= 1 * DD) t1 = rl[p - 1 * DD];
        else { bool ok = ((1 * DD - p + 15) / 16 <= 1) ? ge1 : ge2;
               t1 = ok ? *(const u64*)(ob + 4 * padrel(2 * (p - 1 * DD))) : 0; }
        if (p >= 2 * DD) t2 = rl[p - 2 * DD];
        else { bool ok = ((2 * DD - p + 15) / 16 <= 1) ? ge1 : ge2;
               t2 = ok ? *(const u64*)(ob + 4 * padrel(2 * (p - 2 * DD))) : 0; }
        if (p >= 3 * DD) t3 = rl[p - 3 * DD];
        else { bool ok = ((3 * DD - p + 15) / 16 <= 1) ? ge1 : ge2;
               t3 = ok ? *(const u64*)(ob + 4 * padrel(2 * (p - 3 * DD))) : 0; }
        y2[p] = fma2(b3, t0, fma2(b2, t1, fma2(b1, t2, fma2(b0, t3, y2[p]))));
        rl[p] = fma2(a3, t0, fma2(a2, t1, fma2(a1, t2, mul2(a0, t3))));
    }
#pragma unroll
    for (int p = SF; p < NSLOT; ++p)
        *(u64*)(nb + 8 * p) = rl[p];
}

// ---------- Phase B: tile16 layout (thread (T,r) owns pairs 256T + r + 16j) ----------
template<int DJ, int SF, bool STORE>
__device__ __forceinline__ void levelB(
    u64 (&rl)[NSLOT], u64 (&y2)[NSLOT], const char* ob, char* nb,
    bool tge1, bool tge2,
    u64 a0, u64 a1, u64 a2, u64 a3,
    u64 b0, u64 b1, u64 b2, u64 b3)
{
    __syncthreads();
#pragma unroll
    for (int j = NSLOT - 1; j >= 0; --j) {
        u64 t0 = rl[j];
        u64 t1, t2, t3;
        if (j >= 1 * DJ) t1 = rl[j - 1 * DJ];
        else { bool ok = (1 * DJ - j <= 16) ? tge1 : tge2;
               t1 = ok ? *(const u64*)(ob + 136 * (j - 1 * DJ)) : 0; }
        if (j >= 2 * DJ) t2 = rl[j - 2 * DJ];
        else { bool ok = (2 * DJ - j <= 16) ? tge1 : tge2;
               t2 = ok ? *(const u64*)(ob + 136 * (j - 2 * DJ)) : 0; }
        if (j >= 3 * DJ) t3 = rl[j - 3 * DJ];
        else { bool ok = (3 * DJ - j <= 16) ? tge1 : tge2;
               t3 = ok ? *(const u64*)(ob + 136 * (j - 3 * DJ)) : 0; }
        y2[j] = fma2(b3, t0, fma2(b2, t1, fma2(b1, t2, fma2(b0, t3, y2[j]))));
        rl[j] = fma2(a3, t0, fma2(a2, t1, fma2(a1, t2, mul2(a0, t3))));
    }
    if (STORE) {
#pragma unroll
        for (int j = SF; j < NSLOT; ++j)
            *(u64*)(nb + 136 * j) = rl[j];
    }
}

// ---------- Phase C: cyclic-256 layout (thread owns pairs t + 256k) ----------
template<int DK>
__device__ __forceinline__ void levelC(
    u64 (&rl)[NSLOT], u64 (&y2)[NSLOT],
    u64 a0, u64 a1, u64 a2, u64 a3,
    u64 b0, u64 b1, u64 b2, u64 b3)
{
#pragma unroll
    for (int k = NSLOT - 1; k >= 0; --k) {
        u64 t0 = rl[k];
        u64 t1 = (k >= 1 * DK) ? rl[k - 1 * DK] : 0;
        u64 t2 = (k >= 2 * DK) ? rl[k - 2 * DK] : 0;
        u64 t3 = (k >= 3 * DK) ? rl[k - 3 * DK] : 0;
        y2[k] = fma2(b3, t0, fma2(b2, t1, fma2(b1, t2, fma2(b0, t3, y2[k]))));
        rl[k] = fma2(a3, t0, fma2(a2, t1, fma2(a1, t2, mul2(a0, t3))));
    }
}

__global__ void __launch_bounds__(NTH, 3)
mr_kernel(const float* __restrict__ x, const float* __restrict__ h0,
          const float* __restrict__ h1, const float* __restrict__ w,
          float* __restrict__ out)
{
    extern __shared__ float sm[];
    char* B0 = (char*)sm;
    char* B1 = (char*)sm + BUFB;
    float* scr = (float*)((char*)sm + 2 * BUFB);   // 8 warps x 3 floats

    const int tid  = threadIdx.x;
    const int lane = tid & 31;
    const int warp = tid >> 5;
    const int T    = tid >> 4;        // tile index (tile16 layout)
    const int rr   = tid & 15;        // lane-in-tile
    const int row  = blockIdx.x;      // b*C + c
    const int c    = row & (C_CH - 1);
    const float* xr   = x   + (size_t)row * L_LEN;
    float*       outr = out + (size_t)row * L_LEN;

    const bool ge1  = (tid >= 1), ge2 = (tid >= 2);
    const bool tge1 = (T >= 1),  tge2 = (T >= 2);

    char* blk0 = B0 + 136 * tid;
    char* blk1 = B1 + 136 * tid;
    char* til0 = B0 + 2176 * T + 8 * rr;
    char* til1 = B1 + 2176 * T + 8 * rr;
    char* cyc0 = B0 + 8 * tid + 8 * (tid >> 4);
    char* cyc1 = B1 + 8 * tid + 8 * (tid >> 4);

    // ---- load own 32 elements directly as 16 f32x2 pairs ----
    u64 rl[NSLOT], y2[NSLOT];
    u64 xp[NSLOT];
    {
        const float4* x4 = (const float4*)xr + tid * 8;
#pragma unroll
        for (int i = 0; i < 8; ++i) {
            float4 v = x4[i];
            xp[2 * i]     = pk2(v.x, v.y);
            xp[2 * i + 1] = pk2(v.z, v.w);
        }
    }
    {
        float l14, h14, l15, h15;
        upk2(xp[14], l14, h14);
        upk2(xp[15], l15, h15);
        if (lane == 31) {                 // cross-warp x halo for d=1
            scr[3 * warp + 0] = h14;      // x[29]
            scr[3 * warp + 1] = l15;      // x[30]
            scr[3 * warp + 2] = h15;      // x[31]
        }
    }

    // ---- per-channel coefficients ----
    const int cc = c;
    const float c0 = __ldg(h0 + cc * 4 + 0), c1 = __ldg(h0 + cc * 4 + 1);
    const float c2 = __ldg(h0 + cc * 4 + 2), c3 = __ldg(h0 + cc * 4 + 3);
    const float e0 = __ldg(h1 + cc * 4 + 0), e1 = __ldg(h1 + cc * 4 + 1);
    const float e2 = __ldg(h1 + cc * 4 + 2), e3 = __ldg(h1 + cc * 4 + 3);
    const float* wc = w + cc * (DEPTH_N + 2);

    // x halo elements -1,-2,-3 via shuffle (lane 0 via scratch)
    float xm1, xm2, xm3;
    {
        float l14, h14, l15, h15;
        upk2(xp[14], l14, h14);
        upk2(xp[15], l15, h15);
        xm1 = __shfl_up_sync(0xffffffffu, h15, 1);
        xm2 = __shfl_up_sync(0xffffffffu, l15, 1);
        xm3 = __shfl_up_sync(0xffffffffu, h14, 1);
    }
    __syncthreads();
    if (lane == 0) {
        if (tid > 0) {
            xm1 = scr[3 * (warp - 1) + 2];
            xm2 = scr[3 * (warp - 1) + 1];
            xm3 = scr[3 * (warp - 1) + 0];
        } else { xm1 = 0.0f; xm2 = 0.0f; xm3 = 0.0f; }
    }

    const u64 a0 = pk2(c0, c0), a1 = pk2(c1, c1), a2 = pk2(c2, c2), a3 = pk2(c3, c3);

    // ---- level d=1 in pair form + y init ----
    // y = w13*x + w12*conv(x,h1,1)  (w13 folded into tap-0 coeff); rl = conv(x,h0,1)
    {
        const float w13 = __ldg(wc + 13);
        const float w12 = __ldg(wc + 12);
        const u64 g0 = pk2(w12 * e0, w12 * e0);
        const u64 g1 = pk2(w12 * e1, w12 * e1);
        const u64 g2 = pk2(w12 * e2, w12 * e2);
        const float g3s = w13 + w12 * e3;
        const u64 g3 = pk2(g3s, g3s);
#pragma unroll
        for (int p = 0; p < NSLOT; ++p) {
            float lp, hp; upk2(xp[p], lp, hp); (void)hp;
            u64 t0 = xp[p];
            u64 t1, t2, t3;
            if (p >= 1) {
                float lpm, hpm; upk2(xp[p - 1], lpm, hpm);
                t1 = pk2(hpm, lp);                 // (x[2p-1], x[2p])
                t2 = xp[p - 1];                    // (x[2p-2], x[2p-1])
                if (p >= 2) {
                    float l2, h2; upk2(xp[p - 2], l2, h2); (void)l2;
                    t3 = pk2(h2, lpm);             // (x[2p-3], x[2p-2])
                } else {
                    t3 = pk2(xm1, lpm);            // p==1 -> (x[-1], x[0])? no: (x[-1], x[0])
                }
            } else {
                t1 = pk2(xm1, lp);                 // (x[-1], x[0])
                t2 = pk2(xm2, xm1);                // (x[-2], x[-1])
                t3 = pk2(xm3, xm2);                // (x[-3], x[-2])
            }
            y2[p] = fma2(g3, t0, fma2(g2, t1, fma2(g1, t2, mul2(g0, t3))));
            rl[p] = fma2(a3, t0, fma2(a2, t1, fma2(a1, t2, mul2(a0, t3))));
        }
        // store only the slots d=2's remote taps read (slots 13..15)
#pragma unroll
        for (int p = 13; p < NSLOT; ++p)
            *(u64*)(blk0 + 8 * p) = rl[p];
    }

#define COEFFS(WI)                                                              \
        const float wi = __ldg(wc + (WI));                                      \
        const u64 b0 = pk2(wi * e0, wi * e0);                                   \
        const u64 b1 = pk2(wi * e1, wi * e1);                                   \
        const u64 b2 = pk2(wi * e2, wi * e2);                                   \
        const u64 b3 = pk2(wi * e3, wi * e3);

    // ---- Phase A: d=2,4,8,16 ----
    { COEFFS(11) levelA<1, 10>(rl, y2, blk0, blk1, ge1, ge2, a0, a1, a2, a3, b0, b1, b2, b3); }
    { COEFFS(10) levelA<2,  4>(rl, y2, blk1, blk0, ge1, ge2, a0, a1, a2, a3, b0, b1, b2, b3); }
    { COEFFS( 9) levelA<4,  0>(rl, y2, blk0, blk1, ge1, ge2, a0, a1, a2, a3, b0, b1, b2, b3); }
    { COEFFS( 8) levelA<8,  0>(rl, y2, blk1, blk0, ge1, ge2, a0, a1, a2, a3, b0, b1, b2, b3); }

    // ---- T1: block -> tile16 (y2 through smem; rl re-read from d=16's store) ----
    __syncthreads();
#pragma unroll
    for (int j = 0; j < NSLOT; ++j)
        *(u64*)(blk1 + 8 * j) = y2[j];
    __syncthreads();
#pragma unroll
    for (int j = 0; j < NSLOT; ++j) {
        y2[j] = *(const u64*)(til1 + 136 * j);
        rl[j] = *(const u64*)(til0 + 136 * j);
    }

    // ---- Phase B: d=32,64,128,256 ----
    { COEFFS(7) levelB<1, 10, true >(rl, y2, til0, til1, tge1, tge2, a0, a1, a2, a3, b0, b1, b2, b3); }
    { COEFFS(6) levelB<2,  4, true >(rl, y2, til1, til0, tge1, tge2, a0, a1, a2, a3, b0, b1, b2, b3); }
    { COEFFS(5) levelB<4,  0, true >(rl, y2, til0, til1, tge1, tge2, a0, a1, a2, a3, b0, b1, b2, b3); }
    { COEFFS(4) levelB<8,  0, true >(rl, y2, til1, til0, tge1, tge2, a0, a1, a2, a3, b0, b1, b2, b3); }

    // ---- T2: tile16 -> cyclic-256 ----
    __syncthreads();
#pragma unroll
    for (int j = 0; j < NSLOT; ++j)
        *(u64*)(til1 + 136 * j) = y2[j];
    __syncthreads();
#pragma unroll
    for (int k = 0; k < NSLOT; ++k) {
        y2[k] = *(const u64*)(cyc1 + 2176 * k);
        rl[k] = *(const u64*)(cyc0 + 2176 * k);
    }

    // ---- Phase C: d=512,1024,2048 — pure register ----
    { COEFFS(3) levelC<1>(rl, y2, a0, a1, a2, a3, b0, b1, b2, b3); }
    { COEFFS(2) levelC<2>(rl, y2, a0, a1, a2, a3, b0, b1, b2, b3); }
    { COEFFS(1) levelC<4>(rl, y2, a0, a1, a2, a3, b0, b1, b2, b3); }
#undef COEFFS

    // ---- final: y += w0*res_lo; exact GELU; coalesced STG.64 (cyclic) ----
    {
        const float w0v = __ldg(wc + 0);
        const u64 w0p = pk2(w0v, w0v);
        float2* o2 = (float2*)outr;
#pragma unroll
        for (int k = 0; k < NSLOT; ++k) {
            u64 yf = fma2(w0p, rl[k], y2[k]);
            float lo, hi; upk2(yf, lo, hi);
            lo = 0.5f * lo * (1.0f + erff(lo * 0.70710678118654752f));
            hi = 0.5f * hi * (1.0f + erff(hi * 0.70710678118654752f));
            o2[tid + 256 * k] = make_float2(lo, hi);
        }
    }
}

extern "C" void kernel_launch(void* const* d_in, const int* in_sizes, int n_in,
                              void* d_out, int out_size)
{
    (void)in_sizes; (void)n_in; (void)out_size;
    const float* x  = (const float*)d_in[0];
    const float* h0 = (const float*)d_in[1];
    const float* h1 = (const float*)d_in[2];
    const float* w  = (const float*)d_in[3];
    float* out = (float*)d_out;

    const int smem_bytes = 2 * BUFB + 128;   // 69,760 B
    cudaFuncSetAttribute(mr_kernel, cudaFuncAttributeMaxDynamicSharedMemorySize, smem_bytes);
    mr_kernel<<<B_N * C_CH, NTH, smem_bytes>>>(x, h0, h1, w, out);
}